// round 4
// baseline (speedup 1.0000x reference)
#include <cuda_runtime.h>
#include <cuda_bf16.h>
#include <math.h>

// ---------------- problem constants ----------------
#define NN   768
#define FF   64
#define VV   16
#define NB   8
#define HR   64
#define TT   2
#define ROS  32
#define ROV  16
#define PP   176          // F + V + F + V + V
#define AVGI (1.0f/767.0f)

#define TILE   128
#define BLOCKE 768
#define HP   68           // pitch for H   (16B-aligned rows)
#define ESP  68           // pitch for es
#define EVP  52           // pitch for ev (48 used)

#define SMEM_FLOATS (TILE*HP + TILE*ESP + TILE*EVP + TILE*4 + 512 + 64)
#define SMEM_BYTES  (SMEM_FLOATS*4)

typedef unsigned long long u64;

// ---------------- packed f32x2 helpers (Blackwell) ----------------
__device__ __forceinline__ u64 pack2(float lo, float hi) {
    u64 r; asm("mov.b64 %0,{%1,%2};" : "=l"(r) : "f"(lo), "f"(hi)); return r;
}
__device__ __forceinline__ void unpack2(u64 v, float& lo, float& hi) {
    asm("mov.b64 {%0,%1},%2;" : "=f"(lo), "=f"(hi) : "l"(v));
}
__device__ __forceinline__ u64 fma2(u64 a, u64 b, u64 c) {
    u64 d; asm("fma.rn.f32x2 %0,%1,%2,%3;" : "=l"(d) : "l"(a), "l"(b), "l"(c)); return d;
}

// ---------------- device scratch ----------------
__device__ float g_hsnode[NN*FF];
__device__ float g_hvnode[NN*VV*3];
__device__ float g_hs[NN*FF];
__device__ float g_hv[NN*VV*3];
__device__ float g_aggs[NN*80];
__device__ float g_aggv[NN*288];
__device__ float g_com[3];

// ---------------- init ----------------
__global__ void fill_init(const float* __restrict__ embed) {
    int i = blockIdx.x*blockDim.x + threadIdx.x;
    if (i < NN*FF) g_hsnode[i] = embed[i & 63];
    if (i < NN*VV*3) g_hvnode[i] = 0.f;
}

__global__ void com_kernel(const float* __restrict__ x) {
    __shared__ float s0[24], s1[24], s2[24];
    int i = threadIdx.x;           // 768 threads
    float v0 = x[i*3+0], v1 = x[i*3+1], v2 = x[i*3+2];
    #pragma unroll
    for (int o = 16; o > 0; o >>= 1) {
        v0 += __shfl_down_sync(0xffffffffu, v0, o);
        v1 += __shfl_down_sync(0xffffffffu, v1, o);
        v2 += __shfl_down_sync(0xffffffffu, v2, o);
    }
    if ((i & 31) == 0) { s0[i>>5]=v0; s1[i>>5]=v1; s2[i>>5]=v2; }
    __syncthreads();
    if (i == 0) {
        float a0=0,a1=0,a2=0;
        for (int w = 0; w < 24; w++) { a0+=s0[w]; a1+=s1[w]; a2+=s2[w]; }
        g_com[0]=a0/768.f; g_com[1]=a1/768.f; g_com[2]=a2/768.f;
    }
}

// ---------------- node transform ----------------
__global__ void node_transform(const float* __restrict__ wns,
                               const float* __restrict__ wnv) {
    int n = blockIdx.x, f = threadIdx.x;   // 64 threads
    __shared__ float sh[64], sv[48];
    sh[f] = g_hsnode[n*64 + f];
    if (f < 48) sv[f] = g_hvnode[n*48 + f];
    __syncthreads();
    float acc = 0.f;
    #pragma unroll
    for (int k = 0; k < 64; k++) acc = fmaf(sh[k], wns[k*64 + f], acc);
    g_hs[n*64 + f] = acc;
    if (f < 48) {
        int w = f/3, c = f - w*3;
        float a = 0.f;
        #pragma unroll
        for (int v = 0; v < 16; v++) a = fmaf(sv[v*3 + c], wnv[v*16 + w], a);
        g_hv[n*48 + f] = a;
    }
}

// ---------------- edge aggregation: 1 block per receiver, 768 threads ----------------
__global__ __launch_bounds__(BLOCKE, 1)
void edge_kernel(const float* __restrict__ x,
                 const float* __restrict__ w1, const float* __restrict__ b1,
                 const float* __restrict__ w2, int has_v) {
    extern __shared__ float sm[];
    float* sH  = sm;                       // [TILE][HP]
    float* sES = sH  + TILE*HP;            // [TILE][ESP]
    float* sEV = sES + TILE*ESP;           // [TILE][EVP]
    float* sRH = sEV + TILE*EVP;           // [TILE][4]
    float* sW1 = sRH + TILE*4;             // [8][64]
    float* sB1 = sW1 + 512;                // [64]

    const int tid = threadIdx.x;
    const int rcv = blockIdx.x;

    for (int i = tid; i < 512; i += BLOCKE) sW1[i] = w1[i];
    if (tid < 64) sB1[tid] = b1[tid];

    const float xr0 = x[rcv*3+0], xr1 = x[rcv*3+1], xr2 = x[rcv*3+2];

    // compute-thread mapping: pair = tid>>1 (352 pairs), hh = h-half, eh = edge-half
    const bool act = tid < 704;
    const int hh   = tid & 1;
    const int pair = tid >> 1;                 // 0..351
    const int eh   = (pair >= 176) ? 1 : 0;
    const int p    = act ? (pair - eh*176) : 0;
    int cls, idx0;
    if      (p < 64)  { cls = 0; idx0 = p; }
    else if (p < 80)  { cls = 1; idx0 = p - 64; }
    else if (p < 144) { cls = 2; idx0 = p - 80; }
    else if (p < 160) { cls = 3; idx0 = p - 144; }
    else              { cls = 4; idx0 = p - 160; }
    const bool compute = act && (has_v || cls == 0 || cls == 2);

    // half W2 column: h in [hh*32, hh*32+32)
    u64 wcol2[16];
    if (act) {
        const int hb = hh*32;
        #pragma unroll
        for (int j = 0; j < 16; j++)
            wcol2[j] = pack2(w2[(hb+2*j)*PP + p], w2[(hb+2*j+1)*PP + p]);
    }
    float a0 = 0.f, a1 = 0.f, a2 = 0.f;

    for (int t0 = 0; t0 < NN; t0 += TILE) {
        __syncthreads();   // previous-tile smem reads done
        // stage es / ev (float4 coalesced)
        for (int i = tid; i < TILE*16; i += BLOCKE) {
            int e = i >> 4, f4 = i & 15;
            ((float4*)&sES[e*ESP])[f4] = ((const float4*)&g_hs[(t0+e)*64])[f4];
        }
        if (has_v) {
            for (int i = tid; i < TILE*12; i += BLOCKE) {
                int e = i / 12, f4 = i - e*12;
                ((float4*)&sEV[e*EVP])[f4] = ((const float4*)&g_hv[(t0+e)*48])[f4];
            }
        }
        // ---- phase 1: 768 threads; edge = tid&127, h-group = tid>>7 (0..5) ----
        {
            const int e  = tid & 127;
            const int g  = tid >> 7;        // 0..5
            const int s  = t0 + e;
            const float vx = xr0 - x[s*3+0];
            const float vy = xr1 - x[s*3+1];
            const float vz = xr2 - x[s*3+2];
            const float rr = sqrtf(vx*vx + vy*vy + vz*vz);
            const bool self = (s == rcv);
            const float rinv = self ? 0.f : (1.f / rr);
            if (g == 0) {
                sRH[e*4+0] = vx*rinv;
                sRH[e*4+1] = vy*rinv;
                sRH[e*4+2] = vz*rinv;
            }
            const float rg = self ? 1.f : rr;
            float sa, ca;
            __sincosf(0.31415926535f * rg, &sa, &ca);   // pi/RMAX
            const float coef = 0.4472135955f * rinv;    // sqrt(2/RMAX)/r
            u64 rbp[8];
            {
                float sp = 0.f, sc = sa;
                const float twoc = 2.f*ca;
                #pragma unroll
                for (int nb = 0; nb < 8; nb++) {
                    float rb = sc * coef;
                    rbp[nb] = pack2(rb, rb);
                    float sn = fmaf(twoc, sc, -sp);
                    sp = sc; sc = sn;
                }
            }
            const float u = 2.f * (1.f - rr*0.1f);
            const float env = (!self && u > 0.f) ? 1.2f*__expf(-1.f/u) : 0.f;
            // 32 h-pairs over 6 groups: g0,g1 take 6; g2..g5 take 5
            const int pb = (g < 2) ? g*6 : 12 + (g-2)*5;
            const int np = (g < 2) ? 6 : 5;
            const u64* W1p = (const u64*)sW1;
            const u64* B1p = (const u64*)sB1;
            #pragma unroll
            for (int k = 0; k < 6; k++) {
                if (k < np) {
                    const int h = (pb + k)*2;
                    u64 t2 = B1p[h >> 1];
                    #pragma unroll
                    for (int nb = 0; nb < 8; nb++)
                        t2 = fma2(rbp[nb], W1p[(nb*64 + h) >> 1], t2);
                    float ta, tb; unpack2(t2, ta, tb);
                    const float h0 = env * __fdividef(ta, 1.f + __expf(-ta));
                    const float h1 = env * __fdividef(tb, 1.f + __expf(-tb));
                    *(float2*)&sH[e*HP + h] = make_float2(h0, h1);
                }
            }
        }
        __syncthreads();
        // ---- phase 2: lane-pair split dot products, shfl combine ----
        if (compute) {
            const int ebeg = eh * 64;
            #pragma unroll 1
            for (int e8 = 0; e8 < 64; e8 += 2) {
                const int e0 = ebeg + e8;
                const u64* He0 = (const u64*)&sH[e0*HP] + hh*16;
                const u64* He1 = (const u64*)&sH[(e0+1)*HP] + hh*16;
                u64 q0a = 0ull, q0b = 0ull, q1a = 0ull, q1b = 0ull;
                #pragma unroll
                for (int j = 0; j < 16; j += 4) {
                    ulonglong2 A0 = *(const ulonglong2*)(He0 + j);
                    ulonglong2 A1 = *(const ulonglong2*)(He1 + j);
                    ulonglong2 B0 = *(const ulonglong2*)(He0 + j + 2);
                    ulonglong2 B1 = *(const ulonglong2*)(He1 + j + 2);
                    q0a = fma2(A0.x, wcol2[j+0], q0a);
                    q1a = fma2(A1.x, wcol2[j+0], q1a);
                    q0b = fma2(A0.y, wcol2[j+1], q0b);
                    q1b = fma2(A1.y, wcol2[j+1], q1b);
                    q0a = fma2(B0.x, wcol2[j+2], q0a);
                    q1a = fma2(B1.x, wcol2[j+2], q1a);
                    q0b = fma2(B0.y, wcol2[j+3], q0b);
                    q1b = fma2(B1.y, wcol2[j+3], q1b);
                }
                float u0,v0,u1,v1, w0,x0_,w1,x1_;
                unpack2(q0a, u0, v0); unpack2(q0b, u1, v1);
                unpack2(q1a, w0, x0_); unpack2(q1b, w1, x1_);
                const float r0 = (u0+v0) + (u1+v1);   // partial R(e0) over my h-half
                const float r1 = (w0+x0_) + (w1+x1_); // partial R(e1)
                const float mine  = hh ? r1 : r0;
                const float other = hh ? r0 : r1;
                const float R = mine + __shfl_xor_sync(0xffffffffu, other, 1);
                const int e = e0 + hh;                // even lane -> e0, odd -> e1
                if (cls == 0) {
                    a0 = fmaf(sES[e*ESP + idx0], R, a0);
                } else if (cls == 2) {
                    const float4 rh = *(const float4*)&sRH[e*4];
                    const float t2 = sES[e*ESP + idx0] * R;
                    a0 = fmaf(t2, rh.x, a0);
                    a1 = fmaf(t2, rh.y, a1);
                    a2 = fmaf(t2, rh.z, a2);
                } else if (cls == 1) {
                    const float4 rh = *(const float4*)&sRH[e*4];
                    const float* ev = &sEV[e*EVP + idx0*3];
                    float dot = ev[0]*rh.x + ev[1]*rh.y + ev[2]*rh.z;
                    a0 = fmaf(dot, R, a0);
                } else if (cls == 3) {
                    const float* ev = &sEV[e*EVP + idx0*3];
                    a0 = fmaf(ev[0], R, a0);
                    a1 = fmaf(ev[1], R, a1);
                    a2 = fmaf(ev[2], R, a2);
                } else {
                    const float4 rh = *(const float4*)&sRH[e*4];
                    const float* ev = &sEV[e*EVP + idx0*3];
                    a0 = fmaf(ev[1]*rh.z - ev[2]*rh.y, R, a0);
                    a1 = fmaf(ev[2]*rh.x - ev[0]*rh.z, R, a1);
                    a2 = fmaf(ev[0]*rh.y - ev[1]*rh.x, R, a2);
                }
            }
        }
    }
    // combine lane pair (same p, disjoint edges)
    if (act) {
        a0 += __shfl_xor_sync(0xffffffffu, a0, 1);
        a1 += __shfl_xor_sync(0xffffffffu, a1, 1);
        a2 += __shfl_xor_sync(0xffffffffu, a2, 1);
    }
    __syncthreads();
    if (act && eh == 1 && hh == 0) { sH[p*3+0]=a0; sH[p*3+1]=a1; sH[p*3+2]=a2; }
    __syncthreads();
    if (act && eh == 0 && hh == 0) {
        a0 += sH[p*3+0]; a1 += sH[p*3+1]; a2 += sH[p*3+2];
        if (cls <= 1) {
            g_aggs[rcv*80 + p] = a0 * AVGI;
        } else {
            int row = (cls == 2) ? idx0 : (cls == 3 ? 64 + idx0 : 80 + idx0);
            int base = rcv*288 + row*3;
            g_aggv[base+0] = a0 * AVGI;
            g_aggv[base+1] = a1 * AVGI;
            g_aggv[base+2] = a2 * AVGI;
        }
    }
}

// ---------------- node update ----------------
__global__ void node_update(const float* __restrict__ wmix_s,
                            const float* __restrict__ wmix_v,
                            const float* __restrict__ wgate,
                            const float* __restrict__ wro_s,
                            const float* __restrict__ wro_v,
                            float* __restrict__ out_s,
                            float* __restrict__ out_v,
                            int first, int last) {
    int n = blockIdx.x, t = threadIdx.x;   // 128 threads
    __shared__ float sA[80], sV[288], sM[64], sS[64], sG[16], sMV[48];
    if (t < 80) sA[t] = g_aggs[n*80 + t];
    for (int i = t; i < 288; i += 128) sV[i] = g_aggv[n*288 + i];
    __syncthreads();
    if (t < 64) {
        float m = 0.f;
        #pragma unroll
        for (int p = 0; p < 80; p++) m = fmaf(sA[p], wmix_s[p*64 + t], m);
        sM[t] = m;
        sS[t] = m / (1.f + __expf(-m));
    }
    if (t >= 64 && t < 112) {
        int i = t - 64, v = i/3, c = i - v*3;
        float m = 0.f;
        #pragma unroll
        for (int p = 0; p < 96; p++) m = fmaf(sV[p*3 + c], wmix_v[p*16 + v], m);
        sMV[i] = m;
    }
    __syncthreads();
    if (t < 16) {
        float g = 0.f;
        #pragma unroll
        for (int f = 0; f < 64; f++) g = fmaf(sM[f], wgate[f*16 + t], g);
        sG[t] = 1.f / (1.f + __expf(-g));
    }
    if (t >= 64 && t < 128) g_hsnode[n*64 + (t - 64)] = sS[t - 64];
    __syncthreads();
    if (t < 48) {
        int v = t/3;
        float hv_ = sG[v] * sMV[t];
        g_hvnode[n*48 + t] = hv_;
        sMV[t] = hv_;
    }
    __syncthreads();
    if (t < 32) {
        float o = 0.f;
        #pragma unroll
        for (int f = 0; f < 64; f++) o = fmaf(sS[f], wro_s[f*32 + t], o);
        if (first) out_s[n*32 + t] = o; else out_s[n*32 + t] += o;
    }
    if (t >= 64 && t < 112) {
        int i = t - 64, k = i/3, c = i - k*3;
        float o = 0.f;
        #pragma unroll
        for (int v = 0; v < 16; v++) o = fmaf(sMV[v*3 + c], wro_v[v*16 + k], o);
        float prev = first ? 0.f : out_v[n*48 + i];
        o += prev;
        if (last) o += g_com[c];
        out_v[n*48 + i] = o;
    }
}

// ---------------- launch ----------------
extern "C" void kernel_launch(void* const* d_in, const int* in_sizes, int n_in,
                              void* d_out, int out_size) {
    const float* x      = (const float*)d_in[0];
    const float* embed  = (const float*)d_in[1];
    const float* wns    = (const float*)d_in[2];
    const float* wnv    = (const float*)d_in[3];
    const float* wr1    = (const float*)d_in[4];
    const float* br1    = (const float*)d_in[5];
    const float* wr2    = (const float*)d_in[6];
    const float* wmixs  = (const float*)d_in[7];
    const float* wmixv  = (const float*)d_in[8];
    const float* wgate  = (const float*)d_in[9];
    const float* wros   = (const float*)d_in[10];
    const float* wrov   = (const float*)d_in[11];

    float* out   = (float*)d_out;
    float* out_s = out;                 // [768,32]
    float* out_v = out + NN*ROS;        // [768,16,3]

    cudaFuncSetAttribute(edge_kernel,
        cudaFuncAttributeMaxDynamicSharedMemorySize, SMEM_BYTES);

    fill_init<<<(NN*FF + 255)/256, 256>>>(embed);
    com_kernel<<<1, NN>>>(x);

    for (int t = 0; t < TT; t++) {
        node_transform<<<NN, 64>>>(wns + t*FF*FF, wnv + t*VV*VV);
        edge_kernel<<<NN, BLOCKE, SMEM_BYTES>>>(
            x, wr1 + t*NB*HR, br1 + t*HR, wr2 + t*HR*PP, (t == 0) ? 0 : 1);
        node_update<<<NN, 128>>>(
            wmixs + t*80*64, wmixv + t*96*16, wgate + t*64*16,
            wros + t*64*32, wrov + t*16*16,
            out_s, out_v, (t == 0) ? 1 : 0, (t == TT-1) ? 1 : 0);
    }
}

// round 5
// speedup vs baseline: 1.7798x; 1.7798x over previous
#include <cuda_runtime.h>
#include <cuda_bf16.h>
#include <math.h>

// ---------------- problem constants ----------------
#define NN   768
#define FF   64
#define VV   16
#define NB   8
#define HR   64
#define TT   2
#define ROS  32
#define ROV  16
#define PP   176          // F + V + F + V + V
#define AVGI (1.0f/767.0f)

#define TILE   128
#define BLOCKE 704        // 22 warps: one warp per 8 p-columns
#define NWARP  22

// shared memory float offsets
#define OFF_HTD   0            // u64 [64][128]  : 16384 floats (dup H)
#define OFF_EST   16384        // [64][128]
#define OFF_EVT   24576        // [48][128]
#define OFF_RHT   30720        // [3][128]
#define OFF_W2    31104        // [64][176]
#define OFF_W1    42368        // [8][64]
#define OFF_B1    42880        // [64]
#define OFF_X     42944        // [768*3]
#define SMEM_FLOATS 45248
#define SMEM_BYTES  (SMEM_FLOATS*4)

typedef unsigned long long u64;

// ---------------- packed f32x2 helpers (Blackwell) ----------------
__device__ __forceinline__ u64 pack2(float lo, float hi) {
    u64 r; asm("mov.b64 %0,{%1,%2};" : "=l"(r) : "f"(lo), "f"(hi)); return r;
}
__device__ __forceinline__ void unpack2(u64 v, float& lo, float& hi) {
    asm("mov.b64 {%0,%1},%2;" : "=f"(lo), "=f"(hi) : "l"(v));
}
__device__ __forceinline__ u64 fma2(u64 a, u64 b, u64 c) {
    u64 d; asm("fma.rn.f32x2 %0,%1,%2,%3;" : "=l"(d) : "l"(a), "l"(b), "l"(c)); return d;
}

// ---------------- device scratch ----------------
__device__ float g_hsnode[NN*FF];
__device__ float g_hvnode[NN*VV*3];
__device__ float g_hsT[FF*NN];      // transposed: [f][node]
__device__ float g_hvT[48*NN];      // transposed: [f][node]
__device__ float g_aggs[NN*80];
__device__ float g_aggv[NN*288];
__device__ float g_com[3];

// ---------------- init ----------------
__global__ void fill_init(const float* __restrict__ embed) {
    int i = blockIdx.x*blockDim.x + threadIdx.x;
    if (i < NN*FF) g_hsnode[i] = embed[i & 63];
    if (i < NN*VV*3) g_hvnode[i] = 0.f;
}

__global__ void com_kernel(const float* __restrict__ x) {
    __shared__ float s0[24], s1[24], s2[24];
    int i = threadIdx.x;           // 768 threads
    float v0 = x[i*3+0], v1 = x[i*3+1], v2 = x[i*3+2];
    #pragma unroll
    for (int o = 16; o > 0; o >>= 1) {
        v0 += __shfl_down_sync(0xffffffffu, v0, o);
        v1 += __shfl_down_sync(0xffffffffu, v1, o);
        v2 += __shfl_down_sync(0xffffffffu, v2, o);
    }
    if ((i & 31) == 0) { s0[i>>5]=v0; s1[i>>5]=v1; s2[i>>5]=v2; }
    __syncthreads();
    if (i == 0) {
        float a0=0,a1=0,a2=0;
        for (int w = 0; w < 24; w++) { a0+=s0[w]; a1+=s1[w]; a2+=s2[w]; }
        g_com[0]=a0/768.f; g_com[1]=a1/768.f; g_com[2]=a2/768.f;
    }
}

// ---------------- node transform: writes TRANSPOSED hs/hv ----------------
__global__ void node_transform(const float* __restrict__ wns,
                               const float* __restrict__ wnv) {
    int n = blockIdx.x, f = threadIdx.x;   // 64 threads
    __shared__ float sh[64], sv[48];
    sh[f] = g_hsnode[n*64 + f];
    if (f < 48) sv[f] = g_hvnode[n*48 + f];
    __syncthreads();
    float acc = 0.f;
    #pragma unroll
    for (int k = 0; k < 64; k++) acc = fmaf(sh[k], wns[k*64 + f], acc);
    g_hsT[f*NN + n] = acc;
    if (f < 48) {
        int w = f/3, c = f - w*3;
        float a = 0.f;
        #pragma unroll
        for (int v = 0; v < 16; v++) a = fmaf(sv[v*3 + c], wnv[v*16 + w], a);
        g_hvT[f*NN + n] = a;
    }
}

// ---------------- edge aggregation: 1 block per receiver, 704 threads ----------------
__global__ __launch_bounds__(BLOCKE, 1)
void edge_kernel(const float* __restrict__ x,
                 const float* __restrict__ w1, const float* __restrict__ b1,
                 const float* __restrict__ w2, int has_v) {
    extern __shared__ float sm[];
    u64*   sHTd = (u64*)(sm + OFF_HTD);     // [64][128] dup-f32x2
    float* sEST = sm + OFF_EST;             // [64][128]
    float* sEVT = sm + OFF_EVT;             // [48][128]
    float* sRHT = sm + OFF_RHT;             // [3][128]
    float* sW2  = sm + OFF_W2;              // [64][176]
    float* sW1  = sm + OFF_W1;              // [8][64]
    float* sB1  = sm + OFF_B1;              // [64]
    float* sX   = sm + OFF_X;               // [768*3]

    const int tid  = threadIdx.x;
    const int lane = tid & 31;
    const int w    = tid >> 5;              // warp 0..21 = p-group
    const int rcv  = blockIdx.x;
    const int pbase = w * 8;

    // class per warp
    int cls;
    if      (w < 8)  cls = 0;
    else if (w < 10) cls = 1;
    else if (w < 18) cls = 2;
    else if (w < 20) cls = 3;
    else             cls = 4;
    const bool compute = has_v || cls == 0 || cls == 2;

    // one-time staging
    for (int i = tid; i < 512; i += BLOCKE) sW1[i] = w1[i];
    if (tid < 64) sB1[tid] = b1[tid];
    for (int i = tid; i < PP*64; i += BLOCKE) sW2[i] = w2[i];
    for (int i = tid; i < NN*3; i += BLOCKE) sX[i] = x[i];
    __syncthreads();

    const float xr0 = sX[rcv*3+0], xr1 = sX[rcv*3+1], xr2 = sX[rcv*3+2];

    float acc[24];
    #pragma unroll
    for (int i = 0; i < 24; i++) acc[i] = 0.f;

    for (int t0 = 0; t0 < NN; t0 += TILE) {
        __syncthreads();   // previous tile fully consumed
        // stage es / ev transposed (coalesced read, conflict-free write)
        for (int i = tid; i < 64*TILE; i += BLOCKE) {
            int f = i >> 7, e = i & 127;
            sEST[i] = g_hsT[f*NN + t0 + e];
        }
        if (has_v) {
            for (int i = tid; i < 48*TILE; i += BLOCKE) {
                int f = i >> 7, e = i & 127;
                sEVT[i] = g_hvT[f*NN + t0 + e];
            }
        }
        // ---- phase 1: 512 threads; edge = tid&127, h-group = tid>>7 (0..3) ----
        if (tid < 512) {
            const int e  = tid & 127;
            const int g  = tid >> 7;        // 0..3, 16 h each
            const int s  = t0 + e;
            const float vx = xr0 - sX[s*3+0];
            const float vy = xr1 - sX[s*3+1];
            const float vz = xr2 - sX[s*3+2];
            const float rr = sqrtf(vx*vx + vy*vy + vz*vz);
            const bool self = (s == rcv);
            const float rinv = self ? 0.f : (1.f / rr);
            if (g == 0) {
                sRHT[0*128+e] = vx*rinv;
                sRHT[1*128+e] = vy*rinv;
                sRHT[2*128+e] = vz*rinv;
            }
            const float rg = self ? 1.f : rr;
            float sa, ca;
            __sincosf(0.31415926535f * rg, &sa, &ca);   // pi/RMAX
            const float coef = 0.4472135955f * rinv;    // sqrt(2/RMAX)/r
            u64 rbp[8];
            {
                float sp = 0.f, sc = sa;
                const float twoc = 2.f*ca;
                #pragma unroll
                for (int nb = 0; nb < 8; nb++) {
                    float rb = sc * coef;
                    rbp[nb] = pack2(rb, rb);
                    float sn = fmaf(twoc, sc, -sp);
                    sp = sc; sc = sn;
                }
            }
            const float u = 2.f * (1.f - rr*0.1f);
            const float env = (!self && u > 0.f) ? 1.2f*__expf(-1.f/u) : 0.f;
            const u64* W1p = (const u64*)sW1;
            const u64* B1p = (const u64*)sB1;
            #pragma unroll
            for (int k = 0; k < 8; k++) {
                const int h = g*16 + 2*k;
                u64 t2 = B1p[h >> 1];
                #pragma unroll
                for (int nb = 0; nb < 8; nb++)
                    t2 = fma2(rbp[nb], W1p[(nb*64 + h) >> 1], t2);
                float ta, tb; unpack2(t2, ta, tb);
                const float h0 = env * __fdividef(ta, 1.f + __expf(-ta));
                const float h1 = env * __fdividef(tb, 1.f + __expf(-tb));
                sHTd[h*128 + e]     = pack2(h0, h0);
                sHTd[(h+1)*128 + e] = pack2(h1, h1);
            }
        }
        __syncthreads();
        // ---- phase 2: register-tiled GEMM R[8p][4e] + message accumulation ----
        if (compute) {
            u64 racc[16];   // [pj 0..3][m 0..3]: (R[p0+2pj], R[p0+2pj+1]) for edge lane+32m
            #pragma unroll
            for (int i = 0; i < 16; i++) racc[i] = 0ull;
            #pragma unroll 2
            for (int k = 0; k < 64; k++) {
                const u64* hp = sHTd + k*128 + lane;
                u64 h0 = hp[0], h1 = hp[32], h2 = hp[64], h3 = hp[96];
                const u64* wrow = (const u64*)(sW2 + k*176 + pbase);
                ulonglong2 wA = *(const ulonglong2*)wrow;       // (p0,p1) (p2,p3)
                ulonglong2 wB = *(const ulonglong2*)(wrow + 2); // (p4,p5) (p6,p7)
                racc[0]  = fma2(h0, wA.x, racc[0]);
                racc[1]  = fma2(h1, wA.x, racc[1]);
                racc[2]  = fma2(h2, wA.x, racc[2]);
                racc[3]  = fma2(h3, wA.x, racc[3]);
                racc[4]  = fma2(h0, wA.y, racc[4]);
                racc[5]  = fma2(h1, wA.y, racc[5]);
                racc[6]  = fma2(h2, wA.y, racc[6]);
                racc[7]  = fma2(h3, wA.y, racc[7]);
                racc[8]  = fma2(h0, wB.x, racc[8]);
                racc[9]  = fma2(h1, wB.x, racc[9]);
                racc[10] = fma2(h2, wB.x, racc[10]);
                racc[11] = fma2(h3, wB.x, racc[11]);
                racc[12] = fma2(h0, wB.y, racc[12]);
                racc[13] = fma2(h1, wB.y, racc[13]);
                racc[14] = fma2(h2, wB.y, racc[14]);
                racc[15] = fma2(h3, wB.y, racc[15]);
            }
            // message weighting + accumulate over this tile's 4 edges
            #pragma unroll
            for (int m = 0; m < 4; m++) {
                const int le = lane + 32*m;
                if (cls == 0) {
                    #pragma unroll
                    for (int pj = 0; pj < 4; pj++) {
                        float R0, R1; unpack2(racc[pj*4+m], R0, R1);
                        acc[2*pj]   = fmaf(sEST[(pbase+2*pj)*128 + le],   R0, acc[2*pj]);
                        acc[2*pj+1] = fmaf(sEST[(pbase+2*pj+1)*128 + le], R1, acc[2*pj+1]);
                    }
                } else if (cls == 1) {
                    const float rx = sRHT[le], ry = sRHT[128+le], rz = sRHT[256+le];
                    #pragma unroll
                    for (int pj = 0; pj < 4; pj++) {
                        float R0, R1; unpack2(racc[pj*4+m], R0, R1);
                        const int i0 = pbase + 2*pj - 64;
                        float d0 = sEVT[(i0*3+0)*128+le]*rx + sEVT[(i0*3+1)*128+le]*ry + sEVT[(i0*3+2)*128+le]*rz;
                        float d1 = sEVT[((i0+1)*3+0)*128+le]*rx + sEVT[((i0+1)*3+1)*128+le]*ry + sEVT[((i0+1)*3+2)*128+le]*rz;
                        acc[2*pj]   = fmaf(d0, R0, acc[2*pj]);
                        acc[2*pj+1] = fmaf(d1, R1, acc[2*pj+1]);
                    }
                } else if (cls == 2) {
                    const float rx = sRHT[le], ry = sRHT[128+le], rz = sRHT[256+le];
                    #pragma unroll
                    for (int pj = 0; pj < 4; pj++) {
                        float R0, R1; unpack2(racc[pj*4+m], R0, R1);
                        const int i0 = pbase + 2*pj - 80;
                        const float t0_ = sEST[i0*128 + le] * R0;
                        const float t1_ = sEST[(i0+1)*128 + le] * R1;
                        acc[(2*pj)*3+0] = fmaf(t0_, rx, acc[(2*pj)*3+0]);
                        acc[(2*pj)*3+1] = fmaf(t0_, ry, acc[(2*pj)*3+1]);
                        acc[(2*pj)*3+2] = fmaf(t0_, rz, acc[(2*pj)*3+2]);
                        acc[(2*pj+1)*3+0] = fmaf(t1_, rx, acc[(2*pj+1)*3+0]);
                        acc[(2*pj+1)*3+1] = fmaf(t1_, ry, acc[(2*pj+1)*3+1]);
                        acc[(2*pj+1)*3+2] = fmaf(t1_, rz, acc[(2*pj+1)*3+2]);
                    }
                } else if (cls == 3) {
                    #pragma unroll
                    for (int pj = 0; pj < 4; pj++) {
                        float R0, R1; unpack2(racc[pj*4+m], R0, R1);
                        const int i0 = pbase + 2*pj - 144;
                        #pragma unroll
                        for (int c = 0; c < 3; c++) {
                            acc[(2*pj)*3+c]   = fmaf(sEVT[(i0*3+c)*128+le],     R0, acc[(2*pj)*3+c]);
                            acc[(2*pj+1)*3+c] = fmaf(sEVT[((i0+1)*3+c)*128+le], R1, acc[(2*pj+1)*3+c]);
                        }
                    }
                } else {
                    const float rx = sRHT[le], ry = sRHT[128+le], rz = sRHT[256+le];
                    #pragma unroll
                    for (int pj = 0; pj < 4; pj++) {
                        float R0, R1; unpack2(racc[pj*4+m], R0, R1);
                        const int i0 = pbase + 2*pj - 160;
                        float e0x = sEVT[(i0*3+0)*128+le], e0y = sEVT[(i0*3+1)*128+le], e0z = sEVT[(i0*3+2)*128+le];
                        float e1x = sEVT[((i0+1)*3+0)*128+le], e1y = sEVT[((i0+1)*3+1)*128+le], e1z = sEVT[((i0+1)*3+2)*128+le];
                        acc[(2*pj)*3+0] = fmaf(e0y*rz - e0z*ry, R0, acc[(2*pj)*3+0]);
                        acc[(2*pj)*3+1] = fmaf(e0z*rx - e0x*rz, R0, acc[(2*pj)*3+1]);
                        acc[(2*pj)*3+2] = fmaf(e0x*ry - e0y*rx, R0, acc[(2*pj)*3+2]);
                        acc[(2*pj+1)*3+0] = fmaf(e1y*rz - e1z*ry, R1, acc[(2*pj+1)*3+0]);
                        acc[(2*pj+1)*3+1] = fmaf(e1z*rx - e1x*rz, R1, acc[(2*pj+1)*3+1]);
                        acc[(2*pj+1)*3+2] = fmaf(e1x*ry - e1y*rx, R1, acc[(2*pj+1)*3+2]);
                    }
                }
            }
        }
    }
    // warp butterfly: sum over 32 lanes (e-groups)
    #pragma unroll
    for (int i = 0; i < 24; i++) {
        #pragma unroll
        for (int o = 16; o > 0; o >>= 1)
            acc[i] += __shfl_xor_sync(0xffffffffu, acc[i], o);
    }
    if (lane == 0) {
        if (cls <= 1) {
            #pragma unroll
            for (int j = 0; j < 8; j++)
                g_aggs[rcv*80 + pbase + j] = acc[j] * AVGI;
        } else {
            const int rbase = (cls == 2) ? (pbase - 80) : (cls == 3 ? 64 + (pbase - 144) : 80 + (pbase - 160));
            #pragma unroll
            for (int j = 0; j < 8; j++) {
                const int base = rcv*288 + (rbase + j)*3;
                g_aggv[base+0] = acc[j*3+0] * AVGI;
                g_aggv[base+1] = acc[j*3+1] * AVGI;
                g_aggv[base+2] = acc[j*3+2] * AVGI;
            }
        }
    }
}

// ---------------- node update ----------------
__global__ void node_update(const float* __restrict__ wmix_s,
                            const float* __restrict__ wmix_v,
                            const float* __restrict__ wgate,
                            const float* __restrict__ wro_s,
                            const float* __restrict__ wro_v,
                            float* __restrict__ out_s,
                            float* __restrict__ out_v,
                            int first, int last) {
    int n = blockIdx.x, t = threadIdx.x;   // 128 threads
    __shared__ float sA[80], sV[288], sM[64], sS[64], sG[16], sMV[48];
    if (t < 80) sA[t] = g_aggs[n*80 + t];
    for (int i = t; i < 288; i += 128) sV[i] = g_aggv[n*288 + i];
    __syncthreads();
    if (t < 64) {
        float m = 0.f;
        #pragma unroll
        for (int p = 0; p < 80; p++) m = fmaf(sA[p], wmix_s[p*64 + t], m);
        sM[t] = m;
        sS[t] = m / (1.f + __expf(-m));
    }
    if (t >= 64 && t < 112) {
        int i = t - 64, v = i/3, c = i - v*3;
        float m = 0.f;
        #pragma unroll
        for (int p = 0; p < 96; p++) m = fmaf(sV[p*3 + c], wmix_v[p*16 + v], m);
        sMV[i] = m;
    }
    __syncthreads();
    if (t < 16) {
        float g = 0.f;
        #pragma unroll
        for (int f = 0; f < 64; f++) g = fmaf(sM[f], wgate[f*16 + t], g);
        sG[t] = 1.f / (1.f + __expf(-g));
    }
    if (t >= 64 && t < 128) g_hsnode[n*64 + (t - 64)] = sS[t - 64];
    __syncthreads();
    if (t < 48) {
        int v = t/3;
        float hv_ = sG[v] * sMV[t];
        g_hvnode[n*48 + t] = hv_;
        sMV[t] = hv_;
    }
    __syncthreads();
    if (t < 32) {
        float o = 0.f;
        #pragma unroll
        for (int f = 0; f < 64; f++) o = fmaf(sS[f], wro_s[f*32 + t], o);
        if (first) out_s[n*32 + t] = o; else out_s[n*32 + t] += o;
    }
    if (t >= 64 && t < 112) {
        int i = t - 64, k = i/3, c = i - k*3;
        float o = 0.f;
        #pragma unroll
        for (int v = 0; v < 16; v++) o = fmaf(sMV[v*3 + c], wro_v[v*16 + k], o);
        float prev = first ? 0.f : out_v[n*48 + i];
        o += prev;
        if (last) o += g_com[c];
        out_v[n*48 + i] = o;
    }
}

// ---------------- launch ----------------
extern "C" void kernel_launch(void* const* d_in, const int* in_sizes, int n_in,
                              void* d_out, int out_size) {
    const float* x      = (const float*)d_in[0];
    const float* embed  = (const float*)d_in[1];
    const float* wns    = (const float*)d_in[2];
    const float* wnv    = (const float*)d_in[3];
    const float* wr1    = (const float*)d_in[4];
    const float* br1    = (const float*)d_in[5];
    const float* wr2    = (const float*)d_in[6];
    const float* wmixs  = (const float*)d_in[7];
    const float* wmixv  = (const float*)d_in[8];
    const float* wgate  = (const float*)d_in[9];
    const float* wros   = (const float*)d_in[10];
    const float* wrov   = (const float*)d_in[11];

    float* out   = (float*)d_out;
    float* out_s = out;                 // [768,32]
    float* out_v = out + NN*ROS;        // [768,16,3]

    cudaFuncSetAttribute(edge_kernel,
        cudaFuncAttributeMaxDynamicSharedMemorySize, SMEM_BYTES);

    fill_init<<<(NN*FF + 255)/256, 256>>>(embed);
    com_kernel<<<1, NN>>>(x);

    for (int t = 0; t < TT; t++) {
        node_transform<<<NN, 64>>>(wns + t*FF*FF, wnv + t*VV*VV);
        edge_kernel<<<NN, BLOCKE, SMEM_BYTES>>>(
            x, wr1 + t*NB*HR, br1 + t*HR, wr2 + t*HR*PP, (t == 0) ? 0 : 1);
        node_update<<<NN, 128>>>(
            wmixs + t*80*64, wmixv + t*96*16, wgate + t*64*16,
            wros + t*64*32, wrov + t*16*16,
            out_s, out_v, (t == 0) ? 1 : 0, (t == TT-1) ? 1 : 0);
    }
}

// round 6
// speedup vs baseline: 2.0616x; 1.1584x over previous
#include <cuda_runtime.h>
#include <cuda_bf16.h>
#include <math.h>

// ---------------- problem constants ----------------
#define NN   768
#define FF   64
#define VV   16
#define NB   8
#define HR   64
#define TT   2
#define ROS  32
#define ROV  16
#define PP   176          // F + V + F + V + V
#define AVGI (1.0f/767.0f)

#define TILE   128
#define BLOCKE 704        // 22 warps: one warp per 8 p-columns
#define NWARP  22

// shared memory float offsets
#define OFF_H2    0            // [32][128][2] k-interleaved H : 8192 floats
#define OFF_EST   8192         // [64][128]
#define OFF_EVT   16384        // [48][128]
#define OFF_RHT   22528        // [3][128]
#define OFF_W2    22912        // [64][176]
#define OFF_W1    34176        // [8][64]
#define OFF_B1    34688        // [64]
#define OFF_X     34752        // [768*3]
#define SMEM_FLOATS 37056
#define SMEM_BYTES  (SMEM_FLOATS*4)

typedef unsigned long long u64;

// ---------------- packed f32x2 helpers (Blackwell) ----------------
__device__ __forceinline__ u64 pack2(float lo, float hi) {
    u64 r; asm("mov.b64 %0,{%1,%2};" : "=l"(r) : "f"(lo), "f"(hi)); return r;
}
__device__ __forceinline__ void unpack2(u64 v, float& lo, float& hi) {
    asm("mov.b64 {%0,%1},%2;" : "=f"(lo), "=f"(hi) : "l"(v));
}
__device__ __forceinline__ u64 fma2(u64 a, u64 b, u64 c) {
    u64 d; asm("fma.rn.f32x2 %0,%1,%2,%3;" : "=l"(d) : "l"(a), "l"(b), "l"(c)); return d;
}

// ---------------- device scratch ----------------
__device__ float g_hsnode[NN*FF];
__device__ float g_hvnode[NN*VV*3];
__device__ float g_hsT[FF*NN];      // transposed: [f][node]
__device__ float g_hvT[48*NN];      // transposed: [f][node]
__device__ float g_aggs[NN*80];
__device__ float g_aggv[NN*288];
__device__ float g_com[3];

// ---------------- init ----------------
__global__ void fill_init(const float* __restrict__ embed) {
    int i = blockIdx.x*blockDim.x + threadIdx.x;
    if (i < NN*FF) g_hsnode[i] = embed[i & 63];
    if (i < NN*VV*3) g_hvnode[i] = 0.f;
}

__global__ void com_kernel(const float* __restrict__ x) {
    __shared__ float s0[24], s1[24], s2[24];
    int i = threadIdx.x;           // 768 threads
    float v0 = x[i*3+0], v1 = x[i*3+1], v2 = x[i*3+2];
    #pragma unroll
    for (int o = 16; o > 0; o >>= 1) {
        v0 += __shfl_down_sync(0xffffffffu, v0, o);
        v1 += __shfl_down_sync(0xffffffffu, v1, o);
        v2 += __shfl_down_sync(0xffffffffu, v2, o);
    }
    if ((i & 31) == 0) { s0[i>>5]=v0; s1[i>>5]=v1; s2[i>>5]=v2; }
    __syncthreads();
    if (i == 0) {
        float a0=0,a1=0,a2=0;
        for (int w = 0; w < 24; w++) { a0+=s0[w]; a1+=s1[w]; a2+=s2[w]; }
        g_com[0]=a0/768.f; g_com[1]=a1/768.f; g_com[2]=a2/768.f;
    }
}

// ---------------- node transform: writes TRANSPOSED hs/hv ----------------
__global__ void node_transform(const float* __restrict__ wns,
                               const float* __restrict__ wnv) {
    int n = blockIdx.x, f = threadIdx.x;   // 64 threads
    __shared__ float sh[64], sv[48];
    sh[f] = g_hsnode[n*64 + f];
    if (f < 48) sv[f] = g_hvnode[n*48 + f];
    __syncthreads();
    float acc = 0.f;
    #pragma unroll
    for (int k = 0; k < 64; k++) acc = fmaf(sh[k], wns[k*64 + f], acc);
    g_hsT[f*NN + n] = acc;
    if (f < 48) {
        int w = f/3, c = f - w*3;
        float a = 0.f;
        #pragma unroll
        for (int v = 0; v < 16; v++) a = fmaf(sv[v*3 + c], wnv[v*16 + w], a);
        g_hvT[f*NN + n] = a;
    }
}

// ---------------- edge aggregation: 1 block per receiver, 704 threads ----------------
__global__ __launch_bounds__(BLOCKE, 1)
void edge_kernel(const float* __restrict__ x,
                 const float* __restrict__ w1, const float* __restrict__ b1,
                 const float* __restrict__ w2, int has_v) {
    extern __shared__ float sm[];
    float* sH2  = sm + OFF_H2;              // [32][128][2]
    float* sEST = sm + OFF_EST;             // [64][128]
    float* sEVT = sm + OFF_EVT;             // [48][128]
    float* sRHT = sm + OFF_RHT;             // [3][128]
    float* sW2  = sm + OFF_W2;              // [64][176]
    float* sW1  = sm + OFF_W1;              // [8][64]
    float* sB1  = sm + OFF_B1;              // [64]
    float* sX   = sm + OFF_X;               // [768*3]

    const int tid  = threadIdx.x;
    const int lane = tid & 31;
    const int w    = tid >> 5;              // warp 0..21 = p-group
    const int rcv  = blockIdx.x;
    const int pbase = w * 8;

    // class per warp
    int cls;
    if      (w < 8)  cls = 0;
    else if (w < 10) cls = 1;
    else if (w < 18) cls = 2;
    else if (w < 20) cls = 3;
    else             cls = 4;
    const bool compute = has_v || cls == 0 || cls == 2;

    // one-time staging
    for (int i = tid; i < 512; i += BLOCKE) sW1[i] = w1[i];
    if (tid < 64) sB1[tid] = b1[tid];
    for (int i = tid; i < PP*64; i += BLOCKE) sW2[i] = w2[i];
    for (int i = tid; i < NN*3; i += BLOCKE) sX[i] = x[i];
    __syncthreads();

    const float xr0 = sX[rcv*3+0], xr1 = sX[rcv*3+1], xr2 = sX[rcv*3+2];

    float acc[24];
    #pragma unroll
    for (int i = 0; i < 24; i++) acc[i] = 0.f;

    for (int t0 = 0; t0 < NN; t0 += TILE) {
        __syncthreads();   // previous tile fully consumed
        // stage es / ev transposed (coalesced read, conflict-free write)
        for (int i = tid; i < 64*TILE; i += BLOCKE) {
            int f = i >> 7, e = i & 127;
            sEST[i] = g_hsT[f*NN + t0 + e];
        }
        if (has_v) {
            for (int i = tid; i < 48*TILE; i += BLOCKE) {
                int f = i >> 7, e = i & 127;
                sEVT[i] = g_hvT[f*NN + t0 + e];
            }
        }
        // ---- phase 1: 512 threads; edge = tid&127, h-group = tid>>7 (0..3) ----
        if (tid < 512) {
            const int e  = tid & 127;
            const int g  = tid >> 7;        // 0..3, 16 h each
            const int s  = t0 + e;
            const float vx = xr0 - sX[s*3+0];
            const float vy = xr1 - sX[s*3+1];
            const float vz = xr2 - sX[s*3+2];
            const float rr = sqrtf(vx*vx + vy*vy + vz*vz);
            const bool self = (s == rcv);
            const float rinv = self ? 0.f : (1.f / rr);
            if (g == 0) {
                sRHT[0*128+e] = vx*rinv;
                sRHT[1*128+e] = vy*rinv;
                sRHT[2*128+e] = vz*rinv;
            }
            const float rg = self ? 1.f : rr;
            float sa, ca;
            __sincosf(0.31415926535f * rg, &sa, &ca);   // pi/RMAX
            const float coef = 0.4472135955f * rinv;    // sqrt(2/RMAX)/r
            u64 rbp[8];
            {
                float sp = 0.f, sc = sa;
                const float twoc = 2.f*ca;
                #pragma unroll
                for (int nb = 0; nb < 8; nb++) {
                    float rb = sc * coef;
                    rbp[nb] = pack2(rb, rb);
                    float sn = fmaf(twoc, sc, -sp);
                    sp = sc; sc = sn;
                }
            }
            const float u = 2.f * (1.f - rr*0.1f);
            const float env = (!self && u > 0.f) ? 1.2f*__expf(-1.f/u) : 0.f;
            const u64* W1p = (const u64*)sW1;
            const u64* B1p = (const u64*)sB1;
            #pragma unroll
            for (int k = 0; k < 8; k++) {
                const int h = g*16 + 2*k;
                u64 t2 = B1p[h >> 1];
                #pragma unroll
                for (int nb = 0; nb < 8; nb++)
                    t2 = fma2(rbp[nb], W1p[(nb*64 + h) >> 1], t2);
                float ta, tb; unpack2(t2, ta, tb);
                const float h0 = env * __fdividef(ta, 1.f + __expf(-ta));
                const float h1 = env * __fdividef(tb, 1.f + __expf(-tb));
                // k-interleaved non-dup layout: pair (h, h+1) at [h>>1][e][0..1]
                *(float2*)(sH2 + (h >> 1)*256 + e*2) = make_float2(h0, h1);
            }
        }
        __syncthreads();
        // ---- phase 2: register-tiled GEMM R[8p][4e] + message accumulation ----
        if (compute) {
            u64 racc[16];   // [j 0..3 = p-pair][m 0..3 = edge lane+32m]
            #pragma unroll
            for (int i = 0; i < 16; i++) racc[i] = 0ull;
            #pragma unroll 4
            for (int kk = 0; kk < 32; kk++) {
                const float2* hp = (const float2*)(sH2 + kk*256) + lane;
                float2 f0 = hp[0], f1 = hp[32], f2v = hp[64], f3v = hp[96];
                const u64* w0 = (const u64*)(sW2 + (2*kk)*176 + pbase);
                const u64* w1 = (const u64*)(sW2 + (2*kk+1)*176 + pbase);
                ulonglong2 wA0 = *(const ulonglong2*)w0;
                ulonglong2 wB0 = *(const ulonglong2*)(w0 + 2);
                ulonglong2 wA1 = *(const ulonglong2*)w1;
                ulonglong2 wB1 = *(const ulonglong2*)(w1 + 2);
                u64 d00 = pack2(f0.x, f0.x), d01 = pack2(f0.y, f0.y);
                u64 d10 = pack2(f1.x, f1.x), d11 = pack2(f1.y, f1.y);
                u64 d20 = pack2(f2v.x, f2v.x), d21 = pack2(f2v.y, f2v.y);
                u64 d30 = pack2(f3v.x, f3v.x), d31 = pack2(f3v.y, f3v.y);
                // j=0: wA.x ; j=1: wA.y ; j=2: wB.x ; j=3: wB.y
                racc[0]  = fma2(d00, wA0.x, racc[0]);
                racc[1]  = fma2(d10, wA0.x, racc[1]);
                racc[2]  = fma2(d20, wA0.x, racc[2]);
                racc[3]  = fma2(d30, wA0.x, racc[3]);
                racc[4]  = fma2(d00, wA0.y, racc[4]);
                racc[5]  = fma2(d10, wA0.y, racc[5]);
                racc[6]  = fma2(d20, wA0.y, racc[6]);
                racc[7]  = fma2(d30, wA0.y, racc[7]);
                racc[8]  = fma2(d00, wB0.x, racc[8]);
                racc[9]  = fma2(d10, wB0.x, racc[9]);
                racc[10] = fma2(d20, wB0.x, racc[10]);
                racc[11] = fma2(d30, wB0.x, racc[11]);
                racc[12] = fma2(d00, wB0.y, racc[12]);
                racc[13] = fma2(d10, wB0.y, racc[13]);
                racc[14] = fma2(d20, wB0.y, racc[14]);
                racc[15] = fma2(d30, wB0.y, racc[15]);
                racc[0]  = fma2(d01, wA1.x, racc[0]);
                racc[1]  = fma2(d11, wA1.x, racc[1]);
                racc[2]  = fma2(d21, wA1.x, racc[2]);
                racc[3]  = fma2(d31, wA1.x, racc[3]);
                racc[4]  = fma2(d01, wA1.y, racc[4]);
                racc[5]  = fma2(d11, wA1.y, racc[5]);
                racc[6]  = fma2(d21, wA1.y, racc[6]);
                racc[7]  = fma2(d31, wA1.y, racc[7]);
                racc[8]  = fma2(d01, wB1.x, racc[8]);
                racc[9]  = fma2(d11, wB1.x, racc[9]);
                racc[10] = fma2(d21, wB1.x, racc[10]);
                racc[11] = fma2(d31, wB1.x, racc[11]);
                racc[12] = fma2(d01, wB1.y, racc[12]);
                racc[13] = fma2(d11, wB1.y, racc[13]);
                racc[14] = fma2(d21, wB1.y, racc[14]);
                racc[15] = fma2(d31, wB1.y, racc[15]);
            }
            // message weighting + accumulate over this tile's 4 edges
            #pragma unroll
            for (int m = 0; m < 4; m++) {
                const int le = lane + 32*m;
                if (cls == 0) {
                    #pragma unroll
                    for (int pj = 0; pj < 4; pj++) {
                        float R0, R1; unpack2(racc[pj*4+m], R0, R1);
                        acc[2*pj]   = fmaf(sEST[(pbase+2*pj)*128 + le],   R0, acc[2*pj]);
                        acc[2*pj+1] = fmaf(sEST[(pbase+2*pj+1)*128 + le], R1, acc[2*pj+1]);
                    }
                } else if (cls == 1) {
                    const float rx = sRHT[le], ry = sRHT[128+le], rz = sRHT[256+le];
                    #pragma unroll
                    for (int pj = 0; pj < 4; pj++) {
                        float R0, R1; unpack2(racc[pj*4+m], R0, R1);
                        const int i0 = pbase + 2*pj - 64;
                        float d0 = sEVT[(i0*3+0)*128+le]*rx + sEVT[(i0*3+1)*128+le]*ry + sEVT[(i0*3+2)*128+le]*rz;
                        float d1 = sEVT[((i0+1)*3+0)*128+le]*rx + sEVT[((i0+1)*3+1)*128+le]*ry + sEVT[((i0+1)*3+2)*128+le]*rz;
                        acc[2*pj]   = fmaf(d0, R0, acc[2*pj]);
                        acc[2*pj+1] = fmaf(d1, R1, acc[2*pj+1]);
                    }
                } else if (cls == 2) {
                    const float rx = sRHT[le], ry = sRHT[128+le], rz = sRHT[256+le];
                    #pragma unroll
                    for (int pj = 0; pj < 4; pj++) {
                        float R0, R1; unpack2(racc[pj*4+m], R0, R1);
                        const int i0 = pbase + 2*pj - 80;
                        const float t0_ = sEST[i0*128 + le] * R0;
                        const float t1_ = sEST[(i0+1)*128 + le] * R1;
                        acc[(2*pj)*3+0] = fmaf(t0_, rx, acc[(2*pj)*3+0]);
                        acc[(2*pj)*3+1] = fmaf(t0_, ry, acc[(2*pj)*3+1]);
                        acc[(2*pj)*3+2] = fmaf(t0_, rz, acc[(2*pj)*3+2]);
                        acc[(2*pj+1)*3+0] = fmaf(t1_, rx, acc[(2*pj+1)*3+0]);
                        acc[(2*pj+1)*3+1] = fmaf(t1_, ry, acc[(2*pj+1)*3+1]);
                        acc[(2*pj+1)*3+2] = fmaf(t1_, rz, acc[(2*pj+1)*3+2]);
                    }
                } else if (cls == 3) {
                    #pragma unroll
                    for (int pj = 0; pj < 4; pj++) {
                        float R0, R1; unpack2(racc[pj*4+m], R0, R1);
                        const int i0 = pbase + 2*pj - 144;
                        #pragma unroll
                        for (int c = 0; c < 3; c++) {
                            acc[(2*pj)*3+c]   = fmaf(sEVT[(i0*3+c)*128+le],     R0, acc[(2*pj)*3+c]);
                            acc[(2*pj+1)*3+c] = fmaf(sEVT[((i0+1)*3+c)*128+le], R1, acc[(2*pj+1)*3+c]);
                        }
                    }
                } else {
                    const float rx = sRHT[le], ry = sRHT[128+le], rz = sRHT[256+le];
                    #pragma unroll
                    for (int pj = 0; pj < 4; pj++) {
                        float R0, R1; unpack2(racc[pj*4+m], R0, R1);
                        const int i0 = pbase + 2*pj - 160;
                        float e0x = sEVT[(i0*3+0)*128+le], e0y = sEVT[(i0*3+1)*128+le], e0z = sEVT[(i0*3+2)*128+le];
                        float e1x = sEVT[((i0+1)*3+0)*128+le], e1y = sEVT[((i0+1)*3+1)*128+le], e1z = sEVT[((i0+1)*3+2)*128+le];
                        acc[(2*pj)*3+0] = fmaf(e0y*rz - e0z*ry, R0, acc[(2*pj)*3+0]);
                        acc[(2*pj)*3+1] = fmaf(e0z*rx - e0x*rz, R0, acc[(2*pj)*3+1]);
                        acc[(2*pj)*3+2] = fmaf(e0x*ry - e0y*rx, R0, acc[(2*pj)*3+2]);
                        acc[(2*pj+1)*3+0] = fmaf(e1y*rz - e1z*ry, R1, acc[(2*pj+1)*3+0]);
                        acc[(2*pj+1)*3+1] = fmaf(e1z*rx - e1x*rz, R1, acc[(2*pj+1)*3+1]);
                        acc[(2*pj+1)*3+2] = fmaf(e1x*ry - e1y*rx, R1, acc[(2*pj+1)*3+2]);
                    }
                }
            }
        }
    }
    // warp butterfly: sum over 32 lanes (e-groups)
    #pragma unroll
    for (int i = 0; i < 24; i++) {
        #pragma unroll
        for (int o = 16; o > 0; o >>= 1)
            acc[i] += __shfl_xor_sync(0xffffffffu, acc[i], o);
    }
    if (lane == 0) {
        if (cls <= 1) {
            #pragma unroll
            for (int j = 0; j < 8; j++)
                g_aggs[rcv*80 + pbase + j] = acc[j] * AVGI;
        } else {
            const int rbase = (cls == 2) ? (pbase - 80) : (cls == 3 ? 64 + (pbase - 144) : 80 + (pbase - 160));
            #pragma unroll
            for (int j = 0; j < 8; j++) {
                const int base = rcv*288 + (rbase + j)*3;
                g_aggv[base+0] = acc[j*3+0] * AVGI;
                g_aggv[base+1] = acc[j*3+1] * AVGI;
                g_aggv[base+2] = acc[j*3+2] * AVGI;
            }
        }
    }
}

// ---------------- node update ----------------
__global__ void node_update(const float* __restrict__ wmix_s,
                            const float* __restrict__ wmix_v,
                            const float* __restrict__ wgate,
                            const float* __restrict__ wro_s,
                            const float* __restrict__ wro_v,
                            float* __restrict__ out_s,
                            float* __restrict__ out_v,
                            int first, int last) {
    int n = blockIdx.x, t = threadIdx.x;   // 128 threads
    __shared__ float sA[80], sV[288], sM[64], sS[64], sG[16], sMV[48];
    if (t < 80) sA[t] = g_aggs[n*80 + t];
    for (int i = t; i < 288; i += 128) sV[i] = g_aggv[n*288 + i];
    __syncthreads();
    if (t < 64) {
        float m = 0.f;
        #pragma unroll
        for (int p = 0; p < 80; p++) m = fmaf(sA[p], wmix_s[p*64 + t], m);
        sM[t] = m;
        sS[t] = m / (1.f + __expf(-m));
    }
    if (t >= 64 && t < 112) {
        int i = t - 64, v = i/3, c = i - v*3;
        float m = 0.f;
        #pragma unroll
        for (int p = 0; p < 96; p++) m = fmaf(sV[p*3 + c], wmix_v[p*16 + v], m);
        sMV[i] = m;
    }
    __syncthreads();
    if (t < 16) {
        float g = 0.f;
        #pragma unroll
        for (int f = 0; f < 64; f++) g = fmaf(sM[f], wgate[f*16 + t], g);
        sG[t] = 1.f / (1.f + __expf(-g));
    }
    if (t >= 64 && t < 128) g_hsnode[n*64 + (t - 64)] = sS[t - 64];
    __syncthreads();
    if (t < 48) {
        int v = t/3;
        float hv_ = sG[v] * sMV[t];
        g_hvnode[n*48 + t] = hv_;
        sMV[t] = hv_;
    }
    __syncthreads();
    if (t < 32) {
        float o = 0.f;
        #pragma unroll
        for (int f = 0; f < 64; f++) o = fmaf(sS[f], wro_s[f*32 + t], o);
        if (first) out_s[n*32 + t] = o; else out_s[n*32 + t] += o;
    }
    if (t >= 64 && t < 112) {
        int i = t - 64, k = i/3, c = i - k*3;
        float o = 0.f;
        #pragma unroll
        for (int v = 0; v < 16; v++) o = fmaf(sMV[v*3 + c], wro_v[v*16 + k], o);
        float prev = first ? 0.f : out_v[n*48 + i];
        o += prev;
        if (last) o += g_com[c];
        out_v[n*48 + i] = o;
    }
}

// ---------------- launch ----------------
extern "C" void kernel_launch(void* const* d_in, const int* in_sizes, int n_in,
                              void* d_out, int out_size) {
    const float* x      = (const float*)d_in[0];
    const float* embed  = (const float*)d_in[1];
    const float* wns    = (const float*)d_in[2];
    const float* wnv    = (const float*)d_in[3];
    const float* wr1    = (const float*)d_in[4];
    const float* br1    = (const float*)d_in[5];
    const float* wr2    = (const float*)d_in[6];
    const float* wmixs  = (const float*)d_in[7];
    const float* wmixv  = (const float*)d_in[8];
    const float* wgate  = (const float*)d_in[9];
    const float* wros   = (const float*)d_in[10];
    const float* wrov   = (const float*)d_in[11];

    float* out   = (float*)d_out;
    float* out_s = out;                 // [768,32]
    float* out_v = out + NN*ROS;        // [768,16,3]

    cudaFuncSetAttribute(edge_kernel,
        cudaFuncAttributeMaxDynamicSharedMemorySize, SMEM_BYTES);

    fill_init<<<(NN*FF + 255)/256, 256>>>(embed);
    com_kernel<<<1, NN>>>(x);

    for (int t = 0; t < TT; t++) {
        node_transform<<<NN, 64>>>(wns + t*FF*FF, wnv + t*VV*VV);
        edge_kernel<<<NN, BLOCKE, SMEM_BYTES>>>(
            x, wr1 + t*NB*HR, br1 + t*HR, wr2 + t*HR*PP, (t == 0) ? 0 : 1);
        node_update<<<NN, 128>>>(
            wmixs + t*80*64, wmixv + t*96*16, wgate + t*64*16,
            wros + t*64*32, wrov + t*16*16,
            out_s, out_v, (t == 0) ? 1 : 0, (t == TT-1) ? 1 : 0);
    }
}